// round 12
// baseline (speedup 1.0000x reference)
#include <cuda_runtime.h>
#include <math.h>
#include <float.h>

#define HH 496
#define WW 496
#define NC 9          // sigma x lambda combos
#define NT 8          // thetas
#define NW 31         // windows per dim (496/16)
#define NWIN (NW*NW)  // 961
#define NCOEF (NT*NC*25)

// ---- scratch (static device globals; no allocation) ----
__device__ unsigned long long gCoef2[NCOEF];  // [t][c][25], duplicated (w,w)
__device__ float gOut[NC*HH*WW];              // conv+max result, 8.86 MB
__device__ float gPartial[NC*NWIN];           // per-window channel sums
__device__ float gMaxVal[NC*NWIN];            // per-window channel max
__device__ int   gMaxIdx[NC*NWIN];            // first index of max (0..255)
__device__ float gThr5[NC];                   // mean*5 per channel
__device__ int   gValid[NWIN];                // valid_kp per window

__device__ __constant__ float dThetas[8] = {
    0.39269908169872414f, 0.7853981633974483f, 1.1780972450961724f,
    1.5707963267948966f,  1.9634954084936207f, 2.356194490192345f,
    2.748893571891069f,   3.141592653589793f
};

// ---- packed f32x2 helpers (Blackwell sm_103a) ----
__device__ __forceinline__ unsigned long long pk2(float lo, float hi) {
    unsigned long long r;
    asm("mov.b64 %0, {%1, %2};" : "=l"(r) : "f"(lo), "f"(hi));
    return r;
}
__device__ __forceinline__ void upk2(float& lo, float& hi, unsigned long long v) {
    asm("mov.b64 {%0, %1}, %2;" : "=f"(lo), "=f"(hi) : "l"(v));
}
__device__ __forceinline__ unsigned long long ffma2(unsigned long long a,
                                                    unsigned long long b,
                                                    unsigned long long c) {
    unsigned long long d;
    asm("fma.rn.f32x2 %0, %1, %2, %3;" : "=l"(d) : "l"(a), "l"(b), "l"(c));
    return d;
}

// ============ Kernel 1: Gabor bank (pre-duplicated (w,w) b64) ============
__global__ void gabor_kernel(const float* __restrict__ sigmas,
                             const float* __restrict__ lambdas) {
    int i = blockIdx.x * blockDim.x + threadIdx.x;
    if (i >= NCOEF) return;
    int k = i % 25;
    int c = (i / 25) % NC;
    int t = i / (25 * NC);
    int s = c / 3, l = c % 3;
    float sig = sigmas[s];
    float lam = lambdas[l];
    float th  = dThetas[t];
    int ky = k / 5, kx = k % 5;
    float y = (float)ky - 2.0f;
    float x = (float)kx - 2.0f;
    float st = sinf(th), ct = cosf(th);
    float yth = -x * st + y * ct;
    float xth =  x * ct + y * st;
    float sx = sig;          // sigma_x
    float sy = 2.0f * sig;   // sigma_y = sigma/gamma, gamma=0.5
    float e = expf(-0.5f * (xth*xth/(sx*sx) + yth*yth/(sy*sy)));
    float g = e * cosf(6.283185307179586f * xth / lam + 1.5707963267948966f);
    unsigned int b = __float_as_uint(g);
    gCoef2[(t * NC + c) * 25 + k] = ((unsigned long long)b << 32) | (unsigned long long)b;
}

// ============ Kernel 2: conv + max(theta) + fused window stats ============
// 31x31 blocks of 128 threads; 16x16 output tile == one detection window.
// Thread handles output pixels (gx, gx+8) packed into one f32x2 accumulator.
// Input packs Q[r][k] = (v[tx+k], v[tx+8+k]) : 25 b64, no duplication.
__global__ void __launch_bounds__(128)
conv_kernel(const float* __restrict__ img) {
    __shared__ float sIn[20 * 20];
    __shared__ unsigned long long sCf2[NCOEF];
    __shared__ float sVal[NC][4];
    __shared__ int   sIdx[NC][4];
    __shared__ float sSum[NC][4];

    int tid = threadIdx.x;
    int bx = blockIdx.x, by = blockIdx.y;
    int r0 = by * 16 - 2, c0 = bx * 16 - 2;

    // halo'd input tile (zero pad)
    for (int i = tid; i < 400; i += 128) {
        int r = i / 20, cc = i % 20;
        int gr = r0 + r, gc = c0 + cc;
        sIn[i] = (gr >= 0 && gr < HH && gc >= 0 && gc < WW) ? img[gr * WW + gc] : 0.0f;
    }
    for (int i = tid; i < NCOEF; i += 128) sCf2[i] = gCoef2[i];
    __syncthreads();

    int ty = tid >> 3;        // 0..15
    int tx = tid & 7;         // 0..7  -> pixels tx and tx+8

    unsigned long long Q[5][5];
    #pragma unroll
    for (int r = 0; r < 5; r++) {
        float v[13];
        #pragma unroll
        for (int cc = 0; cc < 13; cc++)
            v[cc] = sIn[(ty + r) * 20 + tx + cc];
        #pragma unroll
        for (int k = 0; k < 5; k++)
            Q[r][k] = pk2(v[k], v[k + 8]);
    }

    float vmax0[NC], vmax1[NC];
    #pragma unroll
    for (int c = 0; c < NC; c++) { vmax0[c] = -FLT_MAX; vmax1[c] = -FLT_MAX; }

    for (int t = 0; t < NT; t++) {
        const unsigned long long* cf = sCf2 + t * NC * 25;
        #pragma unroll
        for (int c = 0; c < NC; c++) {
            unsigned long long acc = 0ull;
            #pragma unroll
            for (int k = 0; k < 25; k++)
                acc = ffma2(Q[k / 5][k % 5], cf[c * 25 + k], acc);
            float a0, a1;
            upk2(a0, a1, acc);
            vmax0[c] = fmaxf(vmax0[c], a0);
            vmax1[c] = fmaxf(vmax1[c], a1);
        }
    }

    // global stores
    int gy = by * 16 + ty;
    int gx = bx * 16 + tx;
    #pragma unroll
    for (int c = 0; c < NC; c++) {
        gOut[c * HH * WW + gy * WW + gx]     = vmax0[c];
        gOut[c * HH * WW + gy * WW + gx + 8] = vmax1[c];
    }

    // fused per-window stats: sum, (max, first flat index)
    int lane = tid & 31, wid = tid >> 5;
    int f0 = ty * 16 + tx;     // flat index within 16x16 (f1 = f0+8)
    #pragma unroll
    for (int c = 0; c < NC; c++) {
        float s = vmax0[c] + vmax1[c];
        float best; int bidx;
        if (vmax0[c] >= vmax1[c]) { best = vmax0[c]; bidx = f0; }      // tie -> smaller f
        else                      { best = vmax1[c]; bidx = f0 + 8; }
        #pragma unroll
        for (int off = 16; off; off >>= 1) {
            s += __shfl_xor_sync(0xffffffffu, s, off);
            float ov = __shfl_xor_sync(0xffffffffu, best, off);
            int   oi = __shfl_xor_sync(0xffffffffu, bidx, off);
            if (ov > best || (ov == best && oi < bidx)) { best = ov; bidx = oi; }
        }
        if (lane == 0) { sVal[c][wid] = best; sIdx[c][wid] = bidx; sSum[c][wid] = s; }
    }
    __syncthreads();
    if (tid < NC) {
        float best = sVal[tid][0]; int bidx = sIdx[tid][0];
        float s = sSum[tid][0];
        #pragma unroll
        for (int k = 1; k < 4; k++) {
            s += sSum[tid][k];
            float ov = sVal[tid][k]; int oi = sIdx[tid][k];
            if (ov > best || (ov == best && oi < bidx)) { best = ov; bidx = oi; }
        }
        int b = by * NW + bx;
        gPartial[tid * NWIN + b] = s;
        gMaxVal[tid * NWIN + b]  = best;
        gMaxIdx[tid * NWIN + b]  = bidx;
    }
}

// ============ Kernel 3: deterministic mean -> thr5 (one block per channel) ==
__global__ void mean_kernel() {
    __shared__ float sh[128];
    int c = blockIdx.x;
    int tid = threadIdx.x;
    float s = 0.0f;
    for (int i = tid; i < NWIN; i += 128) s += gPartial[c * NWIN + i];
    sh[tid] = s;
    __syncthreads();
    if (tid < 64) sh[tid] += sh[tid + 64];
    __syncthreads();
    if (tid < 32) {
        s = sh[tid] + sh[tid + 32];
        #pragma unroll
        for (int off = 16; off; off >>= 1)
            s += __shfl_down_sync(0xffffffffu, s, off);
        if (tid == 0)
            gThr5[c] = (s / (float)(HH * WW)) * 5.0f;
    }
}

// ============ Kernel 4: validity from window stats (exact semantics) ========
// is_max = argmax(thresholded window) == 128.
//  M <= thr          -> all zeros -> argmax = 0 -> false
//  M >  thr, M > 0   -> argmax = first index of M
//  M >  thr, M <= 0  -> exact fallback scan (measure-zero case)
__global__ void valid_kernel() {
    int w = blockIdx.x * blockDim.x + threadIdx.x;
    if (w >= NWIN) return;
    int R = (w / NW) * 16, C = (w % NW) * 16;
    int valid = 0;
    #pragma unroll
    for (int c = 0; c < NC; c++) {
        float thr = gThr5[c];
        float M = gMaxVal[c * NWIN + w];
        if (M > thr) {
            if (M > 0.0f) {
                valid |= (gMaxIdx[c * NWIN + w] == 128);
            } else {
                const float* o = gOut + c * HH * WW;
                float best = -FLT_MAX; int bidx = 0;
                for (int f = 0; f < 256; f++) {
                    float v = o[(R + (f >> 4)) * WW + C + (f & 15)];
                    float tv = (v > thr) ? v : 0.0f;
                    if (tv > best) { best = tv; bidx = f; }
                }
                valid |= (bidx == 128);
            }
        }
    }
    gValid[w] = valid;
}

// ============ Kernel 5: patches (lean: load, any-nonzero, masked write) =====
// grid (961, 9) x 256 threads; 4 elems/thread; float4 fast path for interior.
__global__ void __launch_bounds__(256)
patch_kernel(float* __restrict__ dst) {
    int w = blockIdx.x, c = blockIdx.y;
    int tid = threadIdx.x;
    int wr = (w / NW) * 16 - 8;    // top row of 32x32 patch in image coords
    int wc = (w % NW) * 16 - 8;
    int i  = tid >> 3;             // patch row 0..31
    int j0 = (tid & 7) * 4;        // patch col base
    const float* o = gOut + c * HH * WW;

    int rr = wr + i;
    float4 v;
    bool interior = (wr >= 0) & (wr + 31 < HH) & (wc >= 0) & (wc + 31 < WW);
    if (interior) {
        v = *(const float4*)&o[rr * WW + wc + j0];
    } else {
        bool rok = (rr >= 0 && rr < HH);
        float t[4];
        #pragma unroll
        for (int e = 0; e < 4; e++) {
            int cc = wc + j0 + e;
            t[e] = (rok && cc >= 0 && cc < WW) ? o[rr * WW + cc] : 0.0f;
        }
        v = make_float4(t[0], t[1], t[2], t[3]);
    }

    int nz = (v.x != 0.0f) | (v.y != 0.0f) | (v.z != 0.0f) | (v.w != 0.0f);
    int any = __syncthreads_or(nz);

    float m = (any && gValid[w]) ? 1.0f : 0.0f;
    float4 ov = make_float4(v.x * m, v.y * m, v.z * m, v.w * m);
    ((float4*)dst)[(c * NWIN + w) * 256 + tid] = ov;
}

// ============ launcher ============
extern "C" void kernel_launch(void* const* d_in, const int* in_sizes, int n_in,
                              void* d_out, int out_size) {
    const float* img     = (const float*)d_in[0];
    const float* sigmas  = (const float*)d_in[1];
    const float* lambdas = (const float*)d_in[2];
    float* out = (float*)d_out;

    gabor_kernel<<<(NCOEF + 255) / 256, 256>>>(sigmas, lambdas);
    conv_kernel<<<dim3(NW, NW), 128>>>(img);
    mean_kernel<<<NC, 128>>>();
    valid_kernel<<<(NWIN + 255) / 256, 256>>>();
    patch_kernel<<<dim3(NWIN, NC), 256>>>(out);
}

// round 13
// speedup vs baseline: 1.5046x; 1.5046x over previous
#include <cuda_runtime.h>
#include <math.h>
#include <float.h>

#define HH 496
#define WW 496
#define NC 9          // sigma x lambda combos
#define NT 8          // thetas
#define NW 31         // windows per dim (496/16)
#define NWIN (NW*NW)  // 961
#define NCOEF (NT*NC*25)
#define NFILT (NT*NC)

// ---- scratch (static device globals; no allocation) ----
__device__ float gCoef[NCOEF];                // [t][c][25] dense
__device__ float gOut[NC*HH*WW];              // conv+max result, 8.86 MB
__device__ float gPartial[NC*NWIN];           // per-window channel sums
__device__ float gMaxVal[NC*NWIN];            // per-window channel max
__device__ int   gMaxIdx[NC*NWIN];            // first index of max (0..255)
__device__ float gThr5[NC];                   // mean*5 per channel
__device__ int   gValid[NWIN];                // valid_kp per window

__device__ __constant__ float dThetas[8] = {
    0.39269908169872414f, 0.7853981633974483f, 1.1780972450961724f,
    1.5707963267948966f,  1.9634954084936207f, 2.356194490192345f,
    2.748893571891069f,   3.141592653589793f
};

// ============ Kernel 1: Gabor bank ============
__global__ void gabor_kernel(const float* __restrict__ sigmas,
                             const float* __restrict__ lambdas) {
    int i = blockIdx.x * blockDim.x + threadIdx.x;
    if (i >= NCOEF) return;
    int k = i % 25;
    int c = (i / 25) % NC;
    int t = i / (25 * NC);
    int s = c / 3, l = c % 3;
    float sig = sigmas[s];
    float lam = lambdas[l];
    float th  = dThetas[t];
    int ky = k / 5, kx = k % 5;
    float y = (float)ky - 2.0f;
    float x = (float)kx - 2.0f;
    float st = sinf(th), ct = cosf(th);
    float yth = -x * st + y * ct;
    float xth =  x * ct + y * st;
    float sx = sig;          // sigma_x
    float sy = 2.0f * sig;   // sigma_y = sigma/gamma, gamma=0.5
    float e = expf(-0.5f * (xth*xth/(sx*sx) + yth*yth/(sy*sy)));
    float g = e * cosf(6.283185307179586f * xth / lam + 1.5707963267948966f);
    gCoef[(t * NC + c) * 25 + k] = g;
}

// ============ Kernel 2: conv (scalar FFMA, R2-proven) + window stats ========
// 31x31 blocks of 64 threads; 16x16 output tile == one detection window.
// Thread = 4 horizontal pixels; per coefficient 1 smem load feeds 4 FMAs.
// Coefficient rows padded to 28 floats (112B) so taps load as LDS.128 x6 + 1.
__global__ void __launch_bounds__(64)
conv_kernel(const float* __restrict__ img) {
    __shared__ float sIn[20 * 20];
    __shared__ float sCf[NFILT * 28];   // padded: row f at 28*f, 16B-aligned
    __shared__ float sVal[NC][2];
    __shared__ int   sIdx[NC][2];
    __shared__ float sSum[NC][2];

    int tid = threadIdx.x;
    int bx = blockIdx.x, by = blockIdx.y;
    int r0 = by * 16 - 2, c0 = bx * 16 - 2;

    // halo'd input tile (zero pad)
    for (int i = tid; i < 400; i += 64) {
        int r = i / 20, cc = i % 20;
        int gr = r0 + r, gc = c0 + cc;
        sIn[i] = (gr >= 0 && gr < HH && gc >= 0 && gc < WW) ? img[gr * WW + gc] : 0.0f;
    }
    // coefficients -> padded smem rows
    for (int i = tid; i < NCOEF; i += 64) {
        int f = i / 25, k = i % 25;
        sCf[f * 28 + k] = gCoef[i];
    }
    __syncthreads();

    int ty = tid >> 2;            // 0..15
    int tx = (tid & 3) * 4;       // 0,4,8,12

    float vin[5][8];
    #pragma unroll
    for (int r = 0; r < 5; r++)
        #pragma unroll
        for (int cc = 0; cc < 8; cc++)
            vin[r][cc] = sIn[(ty + r) * 20 + tx + cc];

    float vmax[4][NC];
    #pragma unroll
    for (int p = 0; p < 4; p++)
        #pragma unroll
        for (int c = 0; c < NC; c++) vmax[p][c] = -FLT_MAX;

#define TAP(wv, kk) { const int ky = (kk) / 5, kx = (kk) % 5;                 \
        a0 = fmaf((wv), vin[ky][kx + 0], a0);                                 \
        a1 = fmaf((wv), vin[ky][kx + 1], a1);                                 \
        a2 = fmaf((wv), vin[ky][kx + 2], a2);                                 \
        a3 = fmaf((wv), vin[ky][kx + 3], a3); }

    for (int t = 0; t < NT; t++) {
        #pragma unroll
        for (int c = 0; c < NC; c++) {
            const float* cf = sCf + (t * NC + c) * 28;
            const float4* cf4 = (const float4*)cf;
            float a0 = 0.0f, a1 = 0.0f, a2 = 0.0f, a3 = 0.0f;
            #pragma unroll
            for (int q = 0; q < 6; q++) {
                float4 w = cf4[q];
                TAP(w.x, 4 * q + 0)
                TAP(w.y, 4 * q + 1)
                TAP(w.z, 4 * q + 2)
                TAP(w.w, 4 * q + 3)
            }
            float w24 = cf[24];
            TAP(w24, 24)
            vmax[0][c] = fmaxf(vmax[0][c], a0);
            vmax[1][c] = fmaxf(vmax[1][c], a1);
            vmax[2][c] = fmaxf(vmax[2][c], a2);
            vmax[3][c] = fmaxf(vmax[3][c], a3);
        }
    }
#undef TAP

    // global stores
    int gy = by * 16 + ty;
    int gx = bx * 16 + tx;
    #pragma unroll
    for (int c = 0; c < NC; c++) {
        float4 o = make_float4(vmax[0][c], vmax[1][c], vmax[2][c], vmax[3][c]);
        *(float4*)&gOut[c * HH * WW + gy * WW + gx] = o;
    }

    // fused per-window stats. Flat index within 16x16 for element e of this
    // thread is exactly f = 4*tid + e (ascending), so first-occurrence
    // argmax = min-index tie-breaking across lanes.
    int lane = tid & 31, wid = tid >> 5;
    #pragma unroll
    for (int c = 0; c < NC; c++) {
        float best = vmax[0][c]; int bidx = 4 * tid;
        if (vmax[1][c] > best) { best = vmax[1][c]; bidx = 4 * tid + 1; }
        if (vmax[2][c] > best) { best = vmax[2][c]; bidx = 4 * tid + 2; }
        if (vmax[3][c] > best) { best = vmax[3][c]; bidx = 4 * tid + 3; }
        float s = vmax[0][c] + vmax[1][c] + vmax[2][c] + vmax[3][c];
        #pragma unroll
        for (int off = 16; off; off >>= 1) {
            s += __shfl_xor_sync(0xffffffffu, s, off);
            float ov = __shfl_xor_sync(0xffffffffu, best, off);
            int   oi = __shfl_xor_sync(0xffffffffu, bidx, off);
            if (ov > best || (ov == best && oi < bidx)) { best = ov; bidx = oi; }
        }
        if (lane == 0) { sVal[c][wid] = best; sIdx[c][wid] = bidx; sSum[c][wid] = s; }
    }
    __syncthreads();
    if (tid < NC) {
        float best = sVal[tid][0]; int bidx = sIdx[tid][0];
        float s = sSum[tid][0] + sSum[tid][1];
        float ov = sVal[tid][1]; int oi = sIdx[tid][1];
        if (ov > best || (ov == best && oi < bidx)) { best = ov; bidx = oi; }
        int b = by * NW + bx;
        gPartial[tid * NWIN + b] = s;
        gMaxVal[tid * NWIN + b]  = best;
        gMaxIdx[tid * NWIN + b]  = bidx;
    }
}

// ============ Kernel 3: deterministic mean -> thr5 (one block per channel) ==
__global__ void mean_kernel() {
    __shared__ float sh[128];
    int c = blockIdx.x;
    int tid = threadIdx.x;
    float s = 0.0f;
    for (int i = tid; i < NWIN; i += 128) s += gPartial[c * NWIN + i];
    sh[tid] = s;
    __syncthreads();
    if (tid < 64) sh[tid] += sh[tid + 64];
    __syncthreads();
    if (tid < 32) {
        s = sh[tid] + sh[tid + 32];
        #pragma unroll
        for (int off = 16; off; off >>= 1)
            s += __shfl_down_sync(0xffffffffu, s, off);
        if (tid == 0)
            gThr5[c] = (s / (float)(HH * WW)) * 5.0f;
    }
}

// ============ Kernel 4: validity, branchless fast path ============
// is_max = argmax(thresholded window) == 128.
//  M <= thr          -> all zeros -> argmax = 0 -> false
//  M >  thr, M > 0   -> argmax = first index of M  (fast path)
//  M >  thr, M <= 0  -> exact fallback scan (measure-zero case)
// All fast-path loads are unconditional so they batch into one MLP group.
__global__ void valid_kernel() {
    int w = blockIdx.x * blockDim.x + threadIdx.x;
    if (w >= NWIN) return;
    int valid = 0, fb = 0;
    #pragma unroll
    for (int c = 0; c < NC; c++) {
        float thr = gThr5[c];
        float M   = gMaxVal[c * NWIN + w];
        int   id  = gMaxIdx[c * NWIN + w];
        int gt = (M > thr);
        valid |= gt & (int)(M > 0.0f) & (int)(id == 128);
        fb    |= gt & (int)(M <= 0.0f);
    }
    if (fb) {   // exact recompute (essentially never taken)
        valid = 0;
        int R = (w / NW) * 16, C = (w % NW) * 16;
        for (int c = 0; c < NC; c++) {
            float thr = gThr5[c];
            const float* o = gOut + c * HH * WW;
            float best = -FLT_MAX; int bidx = 0;
            for (int f = 0; f < 256; f++) {
                float v = o[(R + (f >> 4)) * WW + C + (f & 15)];
                float tv = (v > thr) ? v : 0.0f;
                if (tv > best) { best = tv; bidx = f; }
            }
            valid |= (bidx == 128);
        }
    }
    gValid[w] = valid;
}

// ============ Kernel 5: patches (lean: load, any-nonzero, masked write) =====
// grid (961, 9) x 256 threads; 4 elems/thread; float4 fast path for interior.
__global__ void __launch_bounds__(256)
patch_kernel(float* __restrict__ dst) {
    int w = blockIdx.x, c = blockIdx.y;
    int tid = threadIdx.x;
    int wr = (w / NW) * 16 - 8;    // top row of 32x32 patch in image coords
    int wc = (w % NW) * 16 - 8;
    int i  = tid >> 3;             // patch row 0..31
    int j0 = (tid & 7) * 4;        // patch col base
    const float* o = gOut + c * HH * WW;

    int rr = wr + i;
    float4 v;
    bool interior = (wr >= 0) & (wr + 31 < HH) & (wc >= 0) & (wc + 31 < WW);
    if (interior) {
        v = *(const float4*)&o[rr * WW + wc + j0];
    } else {
        bool rok = (rr >= 0 && rr < HH);
        float t[4];
        #pragma unroll
        for (int e = 0; e < 4; e++) {
            int cc = wc + j0 + e;
            t[e] = (rok && cc >= 0 && cc < WW) ? o[rr * WW + cc] : 0.0f;
        }
        v = make_float4(t[0], t[1], t[2], t[3]);
    }

    int nz = (v.x != 0.0f) | (v.y != 0.0f) | (v.z != 0.0f) | (v.w != 0.0f);
    int any = __syncthreads_or(nz);

    float m = (any && gValid[w]) ? 1.0f : 0.0f;
    float4 ov = make_float4(v.x * m, v.y * m, v.z * m, v.w * m);
    ((float4*)dst)[(c * NWIN + w) * 256 + tid] = ov;
}

// ============ launcher ============
extern "C" void kernel_launch(void* const* d_in, const int* in_sizes, int n_in,
                              void* d_out, int out_size) {
    const float* img     = (const float*)d_in[0];
    const float* sigmas  = (const float*)d_in[1];
    const float* lambdas = (const float*)d_in[2];
    float* out = (float*)d_out;

    gabor_kernel<<<(NCOEF + 255) / 256, 256>>>(sigmas, lambdas);
    conv_kernel<<<dim3(NW, NW), 64>>>(img);
    mean_kernel<<<NC, 128>>>();
    valid_kernel<<<(NWIN + 255) / 256, 256>>>();
    patch_kernel<<<dim3(NWIN, NC), 256>>>(out);
}